// round 10
// baseline (speedup 1.0000x reference)
#include <cuda_runtime.h>

#define B_   1024
#define C_   128
#define L_   16
#define EQ_  3
#define E_   10
#define P3_  23
#define P2_  5
#define NP_  136     // symmetric pairs (a<=b)
#define NM_  816     // symmetric triples
#define NDS_ 448     // dual-slots (412 real, padded)
#define NJ3_ 896     // 2*NDS_
#define NJ2_ 192     // pair/x region (136 pairs + 16 x + 40 pad)
#define NF_  1088    // NJ3_ + NJ2_
#define CW_  (EQ_*NF_)

typedef unsigned long long ull;

// Scratch (__device__ globals — no allocation)
__device__ float g_U3sym[EQ_ * NM_ * P3_];
__device__ float g_U2sym[EQ_ * NP_ * P2_];
__device__ __align__(16) float g_coeff[(size_t)E_ * C_ * CW_];   // 16.7 MB
__device__ unsigned short g_dcode[NDS_];             // p | d<<8  (p even)
__device__ unsigned short g_pcode[NJ2_];             // a | b<<4 | isx<<8
__device__ unsigned short g_ds_feat[NJ3_];           // m or 0xFFFF
__device__ int g_cnt[E_];
__device__ int g_nodes[E_ * B_];

__host__ __device__ __forceinline__ int Tet(int d) { return d * (d + 1) * (d + 2) / 6; }

// ---- asm helpers --------------------------------------------------------
__device__ __forceinline__ ull lds_b64(unsigned a) {
    ull v; asm volatile("ld.shared.b64 %0, [%1];" : "=l"(v) : "r"(a)); return v;
}
__device__ __forceinline__ ull lds_b64_B(unsigned a) {   // +640: node-B buffer
    ull v; asm volatile("ld.shared.b64 %0, [%1+640];" : "=l"(v) : "r"(a)); return v;
}
__device__ __forceinline__ void sts_f(unsigned a, float v) {
    asm volatile("st.shared.f32 [%0], %1;" :: "r"(a), "f"(v));
}
__device__ __forceinline__ void sts_f_B(unsigned a, float v) {
    asm volatile("st.shared.f32 [%0+640], %1;" :: "r"(a), "f"(v));
}
__device__ __forceinline__ ull pack2(float lo, float hi) {
    ull d; asm("mov.b64 %0, {%1, %2};" : "=l"(d) : "f"(lo), "f"(hi)); return d;
}
__device__ __forceinline__ void unpack2(float& lo, float& hi, ull v) {
    asm("mov.b64 {%0, %1}, %2;" : "=f"(lo), "=f"(hi) : "l"(v));
}
__device__ __forceinline__ ull mul2(ull a, ull b) {
    ull d; asm("mul.rn.f32x2 %0, %1, %2;" : "=l"(d) : "l"(a), "l"(b)); return d;
}
__device__ __forceinline__ ull fma2(ull a, ull b, ull c) {
    ull d; asm("fma.rn.f32x2 %0, %1, %2, %3;" : "=l"(d) : "l"(a), "l"(b), "l"(c)); return d;
}

// ---------------- launch 1: tables + classify + symmetrize ---------------
// grid 86 x 1024: bid 0 = tables, bid 1 = classify, bid 2..85 = sym
__global__ __launch_bounds__(1024) void k_prep(
    const float* __restrict__ y, const float* __restrict__ U3,
    const float* __restrict__ U2) {
    __shared__ float s[NM_];
    __shared__ int wcnt[32][E_];
    int t = threadIdx.x;
    int bid = blockIdx.x;

    if (bid == 0) {
        for (int j2 = t; j2 < NJ2_; j2 += 1024) {
            unsigned code;
            if (j2 < NP_) {
                int b = 0;
                while ((b + 1) * (b + 2) / 2 <= j2) b++;
                int a = j2 - b * (b + 1) / 2;
                code = (unsigned)a | ((unsigned)b << 4);
            } else if (j2 < NP_ + L_) {
                code = (unsigned)(j2 - NP_) | (1u << 8);
            } else {
                code = (1u << 8);
            }
            g_pcode[j2] = (unsigned short)code;
        }
        if (t < 16) {
            int d = t;
            int off = 0;
            for (int d2 = 0; d2 < d; d2++) { int P = (d2 + 1) * (d2 + 2) / 2; off += (P + 1) >> 1; }
            int P = (d + 1) * (d + 2) / 2;
            for (int p = 0; p < P; p += 2) {
                int ds = off + (p >> 1);
                g_dcode[ds] = (unsigned short)(p | (d << 8));
                g_ds_feat[2 * ds] = (unsigned short)(Tet(d) + p);
                g_ds_feat[2 * ds + 1] = (p + 1 < P) ? (unsigned short)(Tet(d) + p + 1) : (unsigned short)0xFFFF;
            }
        }
        if (t == 16) {
            for (int ds = 412; ds < NDS_; ds++) {
                g_dcode[ds] = 0;
                g_ds_feat[2 * ds] = 0xFFFF;
                g_ds_feat[2 * ds + 1] = 0xFFFF;
            }
        }
    } else if (bid == 1) {
        // atomic-free deterministic classify: 1024 threads = B_
        int b = t;
        int e = 0;
        #pragma unroll
        for (int j = 0; j < E_; j++)
            if (y[b * E_ + j] > 0.5f) e = j;
        int warp = t >> 5, lane = t & 31;
        unsigned m = __match_any_sync(0xffffffffu, e);
        int rank = __popc(m & ((1u << lane) - 1u));
        int ldr = __ffs(m) - 1;
        if (t < 32 * E_) ((int*)wcnt)[t] = 0;
        __syncthreads();
        if (lane == ldr) wcnt[warp][e] = __popc(m);
        __syncthreads();
        int off = 0;
        for (int w = 0; w < warp; w++) off += wcnt[w][e];
        g_nodes[e * B_ + off + rank] = b;
        if (t < E_) {
            int tot = 0;
            #pragma unroll
            for (int w = 0; w < 32; w++) tot += wcnt[w][t];
            g_cnt[t] = tot;
        }
    } else if (bid < 71) {        // 69 U3-sym blocks
        int b2 = bid - 2;
        int w = b2 / P3_, k = b2 % P3_;
        for (int i = t; i < NM_; i += 1024) s[i] = 0.f;
        __syncthreads();
        for (int idx = t; idx < 4096; idx += 1024) {
            int xx = idx >> 8, v = (idx >> 4) & 15, i = idx & 15;
            float val = U3[((((w * L_ + xx) * L_ + v) * L_ + i) * P3_) + k];
            int hi = max(xx, max(v, i));
            int lo = min(xx, min(v, i));
            int mid = xx + v + i - hi - lo;
            int mm = Tet(hi) + mid * (mid + 1) / 2 + lo;
            atomicAdd(&s[mm], val);
        }
        __syncthreads();
        for (int mm = t; mm < NM_; mm += 1024)
            g_U3sym[(w * NM_ + mm) * P3_ + k] = s[mm];
    } else if (bid < 86) {        // 15 U2-sym blocks
        int b2 = bid - 71;
        int w = b2 / P2_, k = b2 % P2_;
        if (t < NP_) s[t] = 0.f;
        __syncthreads();
        if (t < 256) {
            int xx = t >> 4, v = t & 15;
            float val = U2[((w * L_ + xx) * L_ + v) * P2_ + k];
            int hi = max(xx, v), lo = min(xx, v);
            int p = hi * (hi + 1) / 2 + lo;
            atomicAdd(&s[p], val);
        }
        __syncthreads();
        if (t < NP_)
            g_U2sym[(w * NP_ + t) * P2_ + k] = s[t];
    }
}

// ---------------- launch 2: coefficient build + output zeroing -----------
// grid 4104 x 256: bid<840 GEMM tile; bid<3720 pair/x tail; else zero out
__global__ __launch_bounds__(256) void k_coeff(
    const float* __restrict__ wmax, const float* __restrict__ U1,
    const float* __restrict__ w2, const float* __restrict__ w1,
    float* __restrict__ out) {
    __shared__ float us[64][24];
    __shared__ __align__(8) float ws[P3_][64];
    __shared__ float outs[64][65];
    int t = threadIdx.x;
    int bid = blockIdx.x;

    if (bid < 840) {
        int row0 = (bid % 42) * 64;
        int ec0 = (bid / 42) * 64;
        int e = ec0 >> 7, c0 = ec0 & 127;

        for (int idx = t; idx < 64 * P3_; idx += 256) {
            int rr = idx / P3_, k = idx % P3_;
            int row = row0 + rr;
            float v = 0.f;
            if (row < EQ_ * NJ3_) {
                int w = row / NJ3_, jj = row - w * NJ3_;
                int m = g_ds_feat[jj];
                if (m != 0xFFFF) v = g_U3sym[(w * NM_ + m) * P3_ + k];
            }
            us[rr][k] = v;
        }
        for (int idx = t; idx < P3_ * 64; idx += 256) {
            int k = idx >> 6, cc = idx & 63;
            ws[k][cc] = wmax[(e * P3_ + k) * C_ + c0 + cc];
        }
        __syncthreads();

        // f32x2 inner product: thread owns column pair (2*cc2, 2*cc2+1), 8 rows
        int cc2 = t & 31, rg = t >> 5;
        ull wp[P3_];
        #pragma unroll
        for (int k = 0; k < P3_; k++) wp[k] = *(const ull*)&ws[k][cc2 * 2];
        #pragma unroll
        for (int rs = 0; rs < 8; rs++) {
            int rr = rg * 8 + rs;
            ull acc = 0ull;
            #pragma unroll
            for (int k = 0; k < P3_; k++) {
                float u = us[rr][k];
                acc = fma2(pack2(u, u), wp[k], acc);
            }
            float lo, hi; unpack2(lo, hi, acc);
            outs[cc2 * 2][rr] = lo;
            outs[cc2 * 2 + 1][rr] = hi;
        }
        __syncthreads();

        for (int idx = t; idx < 64 * 64; idx += 256) {
            int c2 = idx >> 6, rr = idx & 63;
            int row = row0 + rr;
            if (row < EQ_ * NJ3_) {
                int w = row / NJ3_, jj = row - w * NJ3_;
                g_coeff[(size_t)(ec0 + c2) * CW_ + w * NF_ + jj] = outs[c2][rr];
            }
        }
    } else if (bid < 3720) {
        int i = (bid - 840) * 256 + t;     // exactly 2880*256 = 737280 outputs
        int j2 = i % NJ2_;
        int w  = (i / NJ2_) % EQ_;
        int ec = i / (NJ2_ * EQ_);
        int e = ec >> 7, c = ec & 127;
        float sv = 0.f;
        if (j2 < NP_) {
            #pragma unroll
            for (int k = 0; k < P2_; k++)
                sv += g_U2sym[(w * NP_ + j2) * P2_ + k] * __ldg(&w2[(e * P2_ + k) * C_ + c]);
        } else if (j2 < NP_ + L_) {
            sv = __ldg(&U1[w * L_ + (j2 - NP_)]) * __ldg(&w1[e * C_ + c]);
        }
        g_coeff[(size_t)ec * CW_ + w * NF_ + NJ3_ + j2] = sv;
    } else {
        // zero out: 384 blocks x 256 threads x float4 = 393216 floats exactly
        float4 z = make_float4(0.f, 0.f, 0.f, 0.f);
        ((float4*)out)[(size_t)(bid - 3720) * 256 + t] = z;
    }
}

// ---------------- launch 3: main — block per (c,e), independent warps ----
// Each warp: half = warp&1 of the feature dot for node pair (A, B);
// builds ALL pairs into its PRIVATE zp buffer (no cross-warp deps),
// then atomically adds its half-sum to out. out starts at exact 0 and gets
// exactly 2 adds per element -> bitwise deterministic (float add commutes).
// zp layout per warp: [0,136) pairs, [152] dummy sink; node B at +640 bytes.
// x in registers: lanes 0-15 hold x[i], lanes 16-31 hold 1.0f.
__global__ __launch_bounds__(256, 2) void k_main(
    const float* __restrict__ x, float* __restrict__ out) {
    __shared__ __align__(16) float zp[8][2][160];

    int t = threadIdx.x;
    int warp = t >> 5, lane = t & 31;
    int pw = warp >> 1;
    int half = warp & 1;
    int c = blockIdx.x, e = blockIdx.y;

    const float* cfb = g_coeff + (size_t)(e * C_ + c) * CW_;
    unsigned zbA = (unsigned)__cvta_generic_to_shared(&zp[warp][0][0]);

    // packed dual-step coefficients + private-buffer addresses + x lanes
    ull cd0[7], cd1[7], cd2[7];
    unsigned zsa[7]; int didx[7];
    #pragma unroll
    for (int r = 0; r < 7; r++) {
        int ds = (half * 7 + r) * 32 + lane;
        int j = ds * 2;
        cd0[r] = *(const ull*)(cfb + 0 * NF_ + j);
        cd1[r] = *(const ull*)(cfb + 1 * NF_ + j);
        cd2[r] = *(const ull*)(cfb + 2 * NF_ + j);
        unsigned cc = g_dcode[ds];
        zsa[r] = zbA + (cc & 255u) * 4u;
        didx[r] = cc >> 8;
    }
    // pair/x region: 6 build steps (all pairs), dot coeffs only for owned 3
    int aidx[6], bidx[6]; unsigned sta[5];
    float cp0[3], cp1[3], cp2[3];
    #pragma unroll
    for (int r = 0; r < 6; r++) {
        int j2 = r * 32 + lane;
        unsigned cc = g_pcode[j2];
        aidx[r] = cc & 15u;
        bidx[r] = (cc & 256u) ? 16 : ((cc >> 4) & 15u);
        if (r < 5) sta[r] = (j2 < NP_) ? (zbA + (unsigned)j2 * 4u) : (zbA + 152u * 4u);
    }
    #pragma unroll
    for (int ro = 0; ro < 3; ro++) {
        int j2 = (half * 3 + ro) * 32 + lane;
        cp0[ro] = cfb[0 * NF_ + NJ3_ + j2];
        cp1[ro] = cfb[1 * NF_ + NJ3_ + j2];
        cp2[ro] = cfb[2 * NF_ + NJ3_ + j2];
    }

    int nb = g_cnt[e];
    int jnA = pw * 2;

    int bA = (jnA < nb) ? g_nodes[e * B_ + jnA] : -1;
    int bB = (jnA + 1 < nb) ? g_nodes[e * B_ + jnA + 1] : -1;
    float xnA = 1.0f, xnB = 1.0f;
    if (lane < L_) {
        xnA = (bA >= 0) ? __ldg(&x[((size_t)bA * C_ + c) * L_ + lane]) : 0.f;
        xnB = (bB >= 0) ? __ldg(&x[((size_t)bB * C_ + c) * L_ + lane]) : 0.f;
    }

    for (; jnA < nb; jnA += 8) {
        __syncwarp();          // WAR: previous iter's zp reads vs new stores
        float xvA = xnA, xvB = xnB;
        int bcA = bA, bcB = bB;
        int jn2 = jnA + 8;
        bA = (jn2 < nb) ? g_nodes[e * B_ + jn2] : -1;
        bB = (jn2 + 1 < nb) ? g_nodes[e * B_ + jn2 + 1] : -1;

        // pair/x build (all positions) + dot contribution on owned steps
        float s0A = 0.f, s1A = 0.f, s2A = 0.f;
        float s0B = 0.f, s1B = 0.f, s2B = 0.f;
        #pragma unroll
        for (int r = 0; r < 6; r++) {
            float vaA = __shfl_sync(0xffffffffu, xvA, aidx[r]);
            float vbA = __shfl_sync(0xffffffffu, xvA, bidx[r]);
            float vaB = __shfl_sync(0xffffffffu, xvB, aidx[r]);
            float vbB = __shfl_sync(0xffffffffu, xvB, bidx[r]);
            float valA = vaA * vbA;
            float valB = vaB * vbB;
            if (r < 5) { sts_f(sta[r], valA); sts_f_B(sta[r], valB); }
            bool owned = (half == 0) ? (r < 3) : (r >= 3);
            if (owned) {
                int ro = r - half * 3;
                s0A = fmaf(cp0[ro], valA, s0A);
                s1A = fmaf(cp1[ro], valA, s1A);
                s2A = fmaf(cp2[ro], valA, s2A);
                s0B = fmaf(cp0[ro], valB, s0B);
                s1B = fmaf(cp1[ro], valB, s1B);
                s2B = fmaf(cp2[ro], valB, s2B);
            }
        }
        // next-iteration x prefetch (hidden behind dual phase)
        xnA = 1.0f; xnB = 1.0f;
        if (lane < L_) {
            xnA = (bA >= 0) ? __ldg(&x[((size_t)bA * C_ + c) * L_ + lane]) : 0.f;
            xnB = (bB >= 0) ? __ldg(&x[((size_t)bB * C_ + c) * L_ + lane]) : 0.f;
        }
        __syncwarp();          // pair stores visible to all lanes of this warp

        // fused triple dot: 7 dual steps x 2 nodes, packed f32x2
        ull a0A = 0ull, a1A = 0ull, a2A = 0ull;
        ull a0B = 0ull, a1B = 0ull, a2B = 0ull;
        #pragma unroll
        for (int r = 0; r < 7; r++) {
            ull zA = lds_b64(zsa[r]);
            ull zB = lds_b64_B(zsa[r]);
            float xdA = __shfl_sync(0xffffffffu, xvA, didx[r]);
            float xdB = __shfl_sync(0xffffffffu, xvB, didx[r]);
            ull tpA = mul2(zA, pack2(xdA, xdA));
            ull tpB = mul2(zB, pack2(xdB, xdB));
            a0A = fma2(cd0[r], tpA, a0A);
            a1A = fma2(cd1[r], tpA, a1A);
            a2A = fma2(cd2[r], tpA, a2A);
            a0B = fma2(cd0[r], tpB, a0B);
            a1B = fma2(cd1[r], tpB, a1B);
            a2B = fma2(cd2[r], tpB, a2B);
        }
        float lo, hi;
        unpack2(lo, hi, a0A); float r0A = s0A + lo + hi;
        unpack2(lo, hi, a1A); float r1A = s1A + lo + hi;
        unpack2(lo, hi, a2A); float r2A = s2A + lo + hi;
        unpack2(lo, hi, a0B); float r0B = s0B + lo + hi;
        unpack2(lo, hi, a1B); float r1B = s1B + lo + hi;
        unpack2(lo, hi, a2B); float r2B = s2B + lo + hi;

        // reduce: xor{16,8} on all, select by lane octet, xor{4,2,1}
        #pragma unroll
        for (int msk = 16; msk >= 8; msk >>= 1) {
            r0A += __shfl_xor_sync(0xffffffffu, r0A, msk);
            r1A += __shfl_xor_sync(0xffffffffu, r1A, msk);
            r2A += __shfl_xor_sync(0xffffffffu, r2A, msk);
            r0B += __shfl_xor_sync(0xffffffffu, r0B, msk);
            r1B += __shfl_xor_sync(0xffffffffu, r1B, msk);
            r2B += __shfl_xor_sync(0xffffffffu, r2B, msk);
        }
        float vA = (lane < 8) ? r0A : (lane < 16) ? r1A : r2A;
        float vB = (lane < 8) ? r0B : (lane < 16) ? r1B : r2B;
        #pragma unroll
        for (int msk = 4; msk >= 1; msk >>= 1) {
            vA += __shfl_xor_sync(0xffffffffu, vA, msk);
            vB += __shfl_xor_sync(0xffffffffu, vB, msk);
        }
        // lanes 0/8/16 hold w=0/1/2 sums; fire-and-forget global adds
        if ((lane & 7) == 0 && lane < 24) {
            int w = lane >> 3;
            if (bcA >= 0) atomicAdd(out + ((size_t)bcA * C_ + c) * EQ_ + w, vA);
            if (bcB >= 0) atomicAdd(out + ((size_t)bcB * C_ + c) * EQ_ + w, vB);
        }
    }
}

extern "C" void kernel_launch(void* const* d_in, const int* in_sizes, int n_in,
                              void* d_out, int out_size) {
    const float* x    = (const float*)d_in[0];
    const float* y    = (const float*)d_in[1];
    const float* U3   = (const float*)d_in[2];
    const float* U2   = (const float*)d_in[3];
    const float* U1   = (const float*)d_in[4];
    const float* wmax = (const float*)d_in[5];
    const float* w2   = (const float*)d_in[6];
    const float* w1   = (const float*)d_in[7];
    float* out = (float*)d_out;

    k_prep<<<86, 1024>>>(y, U3, U2);
    k_coeff<<<4104, 256>>>(wmax, U1, w2, w1, out);
    k_main<<<dim3(C_, E_), 256>>>(x, out);
}

// round 12
// speedup vs baseline: 1.3078x; 1.3078x over previous
#include <cuda_runtime.h>

#define B_   1024
#define C_   128
#define L_   16
#define EQ_  3
#define E_   10
#define P3_  23
#define P2_  5
#define NP_  136     // symmetric pairs (a<=b)
#define NM_  816     // symmetric triples
#define NQS_ 256     // quad-slots (210 real, padded to 256)
#define NJ3_ 1024    // 4*NQS_ : triple-region coeff positions
#define NJ2_ 192     // pair/x region (136 pairs + 16 x + 40 pad)
#define NF_  1216    // NJ3_ + NJ2_
#define CW_  (EQ_*NF_)   // 3648

typedef unsigned long long ull;

// Scratch (__device__ globals — no allocation)
__device__ float g_U3sym[EQ_ * NM_ * P3_];
__device__ float g_U2sym[EQ_ * NP_ * P2_];
__device__ __align__(16) float g_coeff[(size_t)E_ * C_ * CW_];   // 18.7 MB
__device__ unsigned short g_qcode[NQS_];             // p | d<<8  (p multiple of 4)
__device__ unsigned short g_pcode[NJ2_];             // a | b<<4 | isx<<8
__device__ unsigned short g_ds_feat[NJ3_];           // m or 0xFFFF
__device__ int g_cnt[E_];
__device__ int g_nodes[E_ * B_];

__host__ __device__ __forceinline__ int Tet(int d) { return d * (d + 1) * (d + 2) / 6; }

// ---- asm helpers --------------------------------------------------------
__device__ __forceinline__ void lds128(unsigned a, ull& x, ull& y) {
    asm volatile("ld.shared.v2.b64 {%0, %1}, [%2];" : "=l"(x), "=l"(y) : "r"(a));
}
__device__ __forceinline__ void lds128_B(unsigned a, ull& x, ull& y) {   // +640: node-B buffer
    asm volatile("ld.shared.v2.b64 {%0, %1}, [%2+640];" : "=l"(x), "=l"(y) : "r"(a));
}
__device__ __forceinline__ void sts_f(unsigned a, float v) {
    asm volatile("st.shared.f32 [%0], %1;" :: "r"(a), "f"(v));
}
__device__ __forceinline__ void sts_f_B(unsigned a, float v) {
    asm volatile("st.shared.f32 [%0+640], %1;" :: "r"(a), "f"(v));
}
__device__ __forceinline__ ull pack2(float lo, float hi) {
    ull d; asm("mov.b64 %0, {%1, %2};" : "=l"(d) : "f"(lo), "f"(hi)); return d;
}
__device__ __forceinline__ void unpack2(float& lo, float& hi, ull v) {
    asm("mov.b64 {%0, %1}, %2;" : "=f"(lo), "=f"(hi) : "l"(v));
}
__device__ __forceinline__ ull mul2(ull a, ull b) {
    ull d; asm("mul.rn.f32x2 %0, %1, %2;" : "=l"(d) : "l"(a), "l"(b)); return d;
}
__device__ __forceinline__ ull fma2(ull a, ull b, ull c) {
    ull d; asm("fma.rn.f32x2 %0, %1, %2, %3;" : "=l"(d) : "l"(a), "l"(b), "l"(c)); return d;
}

// ---------------- launch 1: tables + classify + symmetrize ---------------
// grid 86 x 1024: bid 0 = tables, bid 1 = classify, bid 2..85 = sym
__global__ __launch_bounds__(1024) void k_prep(
    const float* __restrict__ y, const float* __restrict__ U3,
    const float* __restrict__ U2) {
    __shared__ float s[NM_];
    __shared__ int wcnt[32][E_];
    int t = threadIdx.x;
    int bid = blockIdx.x;

    if (bid == 0) {
        for (int j2 = t; j2 < NJ2_; j2 += 1024) {
            unsigned code;
            if (j2 < NP_) {
                int b = 0;
                while ((b + 1) * (b + 2) / 2 <= j2) b++;
                int a = j2 - b * (b + 1) / 2;
                code = (unsigned)a | ((unsigned)b << 4);
            } else if (j2 < NP_ + L_) {
                code = (unsigned)(j2 - NP_) | (1u << 8);
            } else {
                code = (1u << 8);
            }
            g_pcode[j2] = (unsigned short)code;
        }
        // quad-slot tables: slots grouped by d, p in steps of 4
        if (t < 16) {
            int d = t;
            int off = 0;
            for (int d2 = 0; d2 < d; d2++) { int P = (d2 + 1) * (d2 + 2) / 2; off += (P + 3) >> 2; }
            int P = (d + 1) * (d + 2) / 2;
            for (int p = 0; p < P; p += 4) {
                int qs = off + (p >> 2);
                g_qcode[qs] = (unsigned short)(p | (d << 8));
                #pragma unroll
                for (int k = 0; k < 4; k++)
                    g_ds_feat[qs * 4 + k] = (p + k < P) ? (unsigned short)(Tet(d) + p + k)
                                                        : (unsigned short)0xFFFF;
            }
        }
        if (t == 16) {
            for (int qs = 210; qs < NQS_; qs++) {        // 210 real slots
                g_qcode[qs] = 0;
                #pragma unroll
                for (int k = 0; k < 4; k++) g_ds_feat[qs * 4 + k] = 0xFFFF;
            }
        }
    } else if (bid == 1) {
        // atomic-free deterministic classify: 1024 threads = B_
        int b = t;
        int e = 0;
        #pragma unroll
        for (int j = 0; j < E_; j++)
            if (y[b * E_ + j] > 0.5f) e = j;
        int warp = t >> 5, lane = t & 31;
        unsigned m = __match_any_sync(0xffffffffu, e);
        int rank = __popc(m & ((1u << lane) - 1u));
        int ldr = __ffs(m) - 1;
        if (t < 32 * E_) ((int*)wcnt)[t] = 0;
        __syncthreads();
        if (lane == ldr) wcnt[warp][e] = __popc(m);
        __syncthreads();
        int off = 0;
        for (int w = 0; w < warp; w++) off += wcnt[w][e];
        g_nodes[e * B_ + off + rank] = b;
        if (t < E_) {
            int tot = 0;
            #pragma unroll
            for (int w = 0; w < 32; w++) tot += wcnt[w][t];
            g_cnt[t] = tot;
        }
    } else if (bid < 71) {        // 69 U3-sym blocks
        int b2 = bid - 2;
        int w = b2 / P3_, k = b2 % P3_;
        for (int i = t; i < NM_; i += 1024) s[i] = 0.f;
        __syncthreads();
        for (int idx = t; idx < 4096; idx += 1024) {
            int xx = idx >> 8, v = (idx >> 4) & 15, i = idx & 15;
            float val = U3[((((w * L_ + xx) * L_ + v) * L_ + i) * P3_) + k];
            int hi = max(xx, max(v, i));
            int lo = min(xx, min(v, i));
            int mid = xx + v + i - hi - lo;
            int mm = Tet(hi) + mid * (mid + 1) / 2 + lo;
            atomicAdd(&s[mm], val);
        }
        __syncthreads();
        for (int mm = t; mm < NM_; mm += 1024)
            g_U3sym[(w * NM_ + mm) * P3_ + k] = s[mm];
    } else if (bid < 86) {        // 15 U2-sym blocks
        int b2 = bid - 71;
        int w = b2 / P2_, k = b2 % P2_;
        if (t < NP_) s[t] = 0.f;
        __syncthreads();
        if (t < 256) {
            int xx = t >> 4, v = t & 15;
            float val = U2[((w * L_ + xx) * L_ + v) * P2_ + k];
            int hi = max(xx, v), lo = min(xx, v);
            int p = hi * (hi + 1) / 2 + lo;
            atomicAdd(&s[p], val);
        }
        __syncthreads();
        if (t < NP_)
            g_U2sym[(w * NP_ + t) * P2_ + k] = s[t];
    }
}

// ---------------- launch 2: coefficient build ----------------------------
// grid 3840 x 256: bid<960 triple GEMM tile (48 row-tiles x 20 ec-tiles);
//                  else pair/x tail (2880 blocks)
__global__ __launch_bounds__(256) void k_coeff(
    const float* __restrict__ wmax, const float* __restrict__ U1,
    const float* __restrict__ w2, const float* __restrict__ w1) {
    __shared__ float us[64][24];
    __shared__ __align__(8) float ws[P3_][64];
    __shared__ float outs[64][65];
    int t = threadIdx.x;
    int bid = blockIdx.x;

    if (bid < 960) {
        int row0 = (bid % 48) * 64;       // rows = EQ_*NJ3_ = 3072 exactly
        int ec0 = (bid / 48) * 64;
        int e = ec0 >> 7, c0 = ec0 & 127;

        for (int idx = t; idx < 64 * P3_; idx += 256) {
            int rr = idx / P3_, k = idx % P3_;
            int row = row0 + rr;
            int w = row >> 10, jj = row & 1023;       // NJ3_ = 1024
            int m = g_ds_feat[jj];
            us[rr][k] = (m != 0xFFFF) ? g_U3sym[(w * NM_ + m) * P3_ + k] : 0.f;
        }
        for (int idx = t; idx < P3_ * 64; idx += 256) {
            int k = idx >> 6, cc = idx & 63;
            ws[k][cc] = wmax[(e * P3_ + k) * C_ + c0 + cc];
        }
        __syncthreads();

        // f32x2 inner product: thread owns column pair (2*cc2, 2*cc2+1), 8 rows
        int cc2 = t & 31, rg = t >> 5;
        ull wp[P3_];
        #pragma unroll
        for (int k = 0; k < P3_; k++) wp[k] = *(const ull*)&ws[k][cc2 * 2];
        #pragma unroll
        for (int rs = 0; rs < 8; rs++) {
            int rr = rg * 8 + rs;
            ull acc = 0ull;
            #pragma unroll
            for (int k = 0; k < P3_; k++) {
                float u = us[rr][k];
                acc = fma2(pack2(u, u), wp[k], acc);
            }
            float lo, hi; unpack2(lo, hi, acc);
            outs[cc2 * 2][rr] = lo;
            outs[cc2 * 2 + 1][rr] = hi;
        }
        __syncthreads();

        for (int idx = t; idx < 64 * 64; idx += 256) {
            int c2 = idx >> 6, rr = idx & 63;
            int row = row0 + rr;
            int w = row >> 10, jj = row & 1023;
            g_coeff[(size_t)(ec0 + c2) * CW_ + w * NF_ + jj] = outs[c2][rr];
        }
    } else {
        int i = (bid - 960) * 256 + t;     // exactly 2880*256 = 737280 outputs
        int j2 = i % NJ2_;
        int w  = (i / NJ2_) % EQ_;
        int ec = i / (NJ2_ * EQ_);
        int e = ec >> 7, c = ec & 127;
        float sv = 0.f;
        if (j2 < NP_) {
            #pragma unroll
            for (int k = 0; k < P2_; k++)
                sv += g_U2sym[(w * NP_ + j2) * P2_ + k] * __ldg(&w2[(e * P2_ + k) * C_ + c]);
        } else if (j2 < NP_ + L_) {
            sv = __ldg(&U1[w * L_ + (j2 - NP_)]) * __ldg(&w1[e * C_ + c]);
        }
        g_coeff[(size_t)ec * CW_ + w * NF_ + NJ3_ + j2] = sv;
    }
}

// ---------------- launch 3: main — block per (c,e) -----------------------
// 4 warp-pairs per block; each pair processes 2 nodes per iteration.
// Pair pw owns zp[pw][0] (node A) and zp[pw][1] (node B, +640 bytes).
// Buffer layout: [0,136) pair values; [152] dummy store sink.
// x in registers: lanes 0-15 hold x[i], lanes 16-31 hold 1.0f.
__global__ __launch_bounds__(256, 2) void k_main(
    const float* __restrict__ x, float* __restrict__ out) {
    __shared__ __align__(16) float zp[4][2][160];
    __shared__ float s_red[4][6];

    int t = threadIdx.x;
    int warp = t >> 5, lane = t & 31;
    int pw = warp >> 1;
    int half = warp & 1;
    int c = blockIdx.x, e = blockIdx.y;

    const float* cfb = g_coeff + (size_t)(e * C_ + c) * CW_;
    unsigned zbA = (unsigned)__cvta_generic_to_shared(&zp[pw][0][0]);

    // quad-step coefficients (2 ull per step per w) + addresses + x lanes
    ull cd0[8], cd1[8], cd2[8];
    unsigned zsa[4]; int didx[4];
    #pragma unroll
    for (int r = 0; r < 4; r++) {
        int slot = (half * 4 + r) * 32 + lane;
        int j = slot * 4;
        cd0[2*r]   = *(const ull*)(cfb + 0 * NF_ + j);
        cd0[2*r+1] = *(const ull*)(cfb + 0 * NF_ + j + 2);
        cd1[2*r]   = *(const ull*)(cfb + 1 * NF_ + j);
        cd1[2*r+1] = *(const ull*)(cfb + 1 * NF_ + j + 2);
        cd2[2*r]   = *(const ull*)(cfb + 2 * NF_ + j);
        cd2[2*r+1] = *(const ull*)(cfb + 2 * NF_ + j + 2);
        unsigned cc = g_qcode[slot];
        zsa[r] = zbA + (cc & 255u) * 4u;
        didx[r] = cc >> 8;
    }
    // pair-region coefficients + shfl source lanes + store addresses
    float cp0[3], cp1[3], cp2[3];
    int aidx[3], bidx[3]; unsigned sta[3];
    #pragma unroll
    for (int r = 0; r < 3; r++) {
        int j2 = (half * 3 + r) * 32 + lane;
        cp0[r] = cfb[0 * NF_ + NJ3_ + j2];
        cp1[r] = cfb[1 * NF_ + NJ3_ + j2];
        cp2[r] = cfb[2 * NF_ + NJ3_ + j2];
        unsigned cc = g_pcode[j2];
        aidx[r] = cc & 15u;
        bidx[r] = (cc & 256u) ? 16 : ((cc >> 4) & 15u);  // pairs: b lane; isx/pad: lane 16 (=1.0f)
        sta[r] = (j2 < NP_) ? (zbA + (unsigned)j2 * 4u) : (zbA + 152u * 4u);
    }

    int nb = g_cnt[e];
    int jnA = pw * 2;

    // prime: node indices + x prefetch for first iteration
    int bA = (jnA < nb) ? g_nodes[e * B_ + jnA] : -1;
    int bB = (jnA + 1 < nb) ? g_nodes[e * B_ + jnA + 1] : -1;
    float xnA = 1.0f, xnB = 1.0f;
    if (lane < L_) {
        xnA = (bA >= 0) ? __ldg(&x[((size_t)bA * C_ + c) * L_ + lane]) : 0.f;
        xnB = (bB >= 0) ? __ldg(&x[((size_t)bB * C_ + c) * L_ + lane]) : 0.f;
    }

    int wsel = lane >> 3;                 // 0..3 (octet id; 3 unused)
    bool owner = (lane == 0) | (lane == 8) | (lane == 16);

    #define PBAR() asm volatile("bar.sync %0, 64;" :: "r"(pw + 1) : "memory")

    for (; jnA < nb; jnA += 8) {
        float xvA = xnA, xvB = xnB;
        int bcA = bA, bcB = bB;
        int jn2 = jnA + 8;
        bA = (jn2 < nb) ? g_nodes[e * B_ + jn2] : -1;
        bB = (jn2 + 1 < nb) ? g_nodes[e * B_ + jn2 + 1] : -1;

        // pair/x region for both nodes: value -> dot contribution + zp store
        float s0A = 0.f, s1A = 0.f, s2A = 0.f;
        float s0B = 0.f, s1B = 0.f, s2B = 0.f;
        #pragma unroll
        for (int r = 0; r < 3; r++) {
            float vaA = __shfl_sync(0xffffffffu, xvA, aidx[r]);
            float vbA = __shfl_sync(0xffffffffu, xvA, bidx[r]);
            float vaB = __shfl_sync(0xffffffffu, xvB, aidx[r]);
            float vbB = __shfl_sync(0xffffffffu, xvB, bidx[r]);
            float valA = vaA * vbA;
            float valB = vaB * vbB;
            sts_f(sta[r], valA);
            sts_f_B(sta[r], valB);
            s0A = fmaf(cp0[r], valA, s0A);
            s1A = fmaf(cp1[r], valA, s1A);
            s2A = fmaf(cp2[r], valA, s2A);
            s0B = fmaf(cp0[r], valB, s0B);
            s1B = fmaf(cp1[r], valB, s1B);
            s2B = fmaf(cp2[r], valB, s2B);
        }
        // next-iteration x prefetch (hidden behind quad phase)
        xnA = 1.0f; xnB = 1.0f;
        if (lane < L_) {
            xnA = (bA >= 0) ? __ldg(&x[((size_t)bA * C_ + c) * L_ + lane]) : 0.f;
            xnB = (bB >= 0) ? __ldg(&x[((size_t)bB * C_ + c) * L_ + lane]) : 0.f;
        }

        PBAR();   // zp (both buffers) visible across the warp pair

        // fused triple dot: 4 quad steps x 2 nodes, packed f32x2
        ull a0A = 0ull, a1A = 0ull, a2A = 0ull;
        ull a0B = 0ull, a1B = 0ull, a2B = 0ull;
        #pragma unroll
        for (int r = 0; r < 4; r++) {
            ull zA0, zA1, zB0, zB1;
            lds128(zsa[r], zA0, zA1);
            lds128_B(zsa[r], zB0, zB1);
            float xdA = __shfl_sync(0xffffffffu, xvA, didx[r]);
            float xdB = __shfl_sync(0xffffffffu, xvB, didx[r]);
            ull xpA = pack2(xdA, xdA);
            ull xpB = pack2(xdB, xdB);
            ull tA0 = mul2(zA0, xpA), tA1 = mul2(zA1, xpA);
            ull tB0 = mul2(zB0, xpB), tB1 = mul2(zB1, xpB);
            a0A = fma2(cd0[2*r], tA0, a0A); a0A = fma2(cd0[2*r+1], tA1, a0A);
            a1A = fma2(cd1[2*r], tA0, a1A); a1A = fma2(cd1[2*r+1], tA1, a1A);
            a2A = fma2(cd2[2*r], tA0, a2A); a2A = fma2(cd2[2*r+1], tA1, a2A);
            a0B = fma2(cd0[2*r], tB0, a0B); a0B = fma2(cd0[2*r+1], tB1, a0B);
            a1B = fma2(cd1[2*r], tB0, a1B); a1B = fma2(cd1[2*r+1], tB1, a1B);
            a2B = fma2(cd2[2*r], tB0, a2B); a2B = fma2(cd2[2*r+1], tB1, a2B);
        }
        float lo, hi;
        unpack2(lo, hi, a0A); float r0A = s0A + lo + hi;
        unpack2(lo, hi, a1A); float r1A = s1A + lo + hi;
        unpack2(lo, hi, a2A); float r2A = s2A + lo + hi;
        unpack2(lo, hi, a0B); float r0B = s0B + lo + hi;
        unpack2(lo, hi, a1B); float r1B = s1B + lo + hi;
        unpack2(lo, hi, a2B); float r2B = s2B + lo + hi;

        // reduce: xor{16,8} on all six, octet-select, xor{4,2,1}
        #pragma unroll
        for (int msk = 16; msk >= 8; msk >>= 1) {
            r0A += __shfl_xor_sync(0xffffffffu, r0A, msk);
            r1A += __shfl_xor_sync(0xffffffffu, r1A, msk);
            r2A += __shfl_xor_sync(0xffffffffu, r2A, msk);
            r0B += __shfl_xor_sync(0xffffffffu, r0B, msk);
            r1B += __shfl_xor_sync(0xffffffffu, r1B, msk);
            r2B += __shfl_xor_sync(0xffffffffu, r2B, msk);
        }
        float vA = (lane < 8) ? r0A : (lane < 16) ? r1A : r2A;
        float vB = (lane < 8) ? r0B : (lane < 16) ? r1B : r2B;
        #pragma unroll
        for (int msk = 4; msk >= 1; msk >>= 1) {
            vA += __shfl_xor_sync(0xffffffffu, vA, msk);
            vB += __shfl_xor_sync(0xffffffffu, vB, msk);
        }
        // lanes 0/8/16 hold w=0/1/2 totals for this half
        if (owner) {
            if (half == 1) s_red[pw][wsel] = vA;       // half1 publishes A
            else           s_red[pw][3 + wsel] = vB;   // half0 publishes B
        }
        PBAR();   // exchange halves; also protects zp/s_red overwrite next iter
        if (owner) {
            if (half == 0) {
                if (bcA >= 0)
                    out[((size_t)bcA * C_ + c) * EQ_ + wsel] = vA + s_red[pw][wsel];
            } else {
                if (bcB >= 0)
                    out[((size_t)bcB * C_ + c) * EQ_ + wsel] = vB + s_red[pw][3 + wsel];
            }
        }
    }
    #undef PBAR
}

extern "C" void kernel_launch(void* const* d_in, const int* in_sizes, int n_in,
                              void* d_out, int out_size) {
    const float* x    = (const float*)d_in[0];
    const float* y    = (const float*)d_in[1];
    const float* U3   = (const float*)d_in[2];
    const float* U2   = (const float*)d_in[3];
    const float* U1   = (const float*)d_in[4];
    const float* wmax = (const float*)d_in[5];
    const float* w2   = (const float*)d_in[6];
    const float* w1   = (const float*)d_in[7];
    float* out = (float*)d_out;

    k_prep<<<86, 1024>>>(y, U3, U2);
    k_coeff<<<3840, 256>>>(wmax, U1, w2, w1);
    k_main<<<dim3(C_, E_), 256>>>(x, out);
}

// round 15
// speedup vs baseline: 1.3443x; 1.0280x over previous
#include <cuda_runtime.h>

#define B_   1024
#define C_   128
#define L_   16
#define EQ_  3
#define E_   10
#define P3_  23
#define P2_  5
#define NP_  136     // symmetric pairs (a<=b)
#define NM_  816     // symmetric triples
#define NQS_ 256     // quad-slots (210 real, padded to 256)
#define NJ3_ 1024    // 4*NQS_ : triple-region coeff positions
#define NJ2_ 192     // pair/x region (136 pairs + 16 x + 40 pad)
#define NF_  1216    // NJ3_ + NJ2_
#define CW_  (EQ_*NF_)   // 3648

typedef unsigned long long ull;

// Scratch (__device__ globals — no allocation)
__device__ float g_U3sym[EQ_ * NM_ * P3_];
__device__ float g_U2sym[EQ_ * NP_ * P2_];
__device__ __align__(16) float g_coeff[(size_t)E_ * C_ * CW_];   // 18.7 MB
__device__ unsigned short g_qcode[NQS_];             // p | d<<8  (p multiple of 4)
__device__ unsigned short g_pcode[NJ2_];             // a | b<<4 | isx<<8
__device__ unsigned short g_ds_feat[NJ3_];           // m or 0xFFFF
__device__ int g_cnt[E_];
__device__ int g_nodes[E_ * B_];

__host__ __device__ __forceinline__ int Tet(int d) { return d * (d + 1) * (d + 2) / 6; }

// ---- asm helpers --------------------------------------------------------
__device__ __forceinline__ void lds128(unsigned a, ull& x, ull& y) {
    asm volatile("ld.shared.v2.b64 {%0, %1}, [%2];" : "=l"(x), "=l"(y) : "r"(a));
}
__device__ __forceinline__ void lds128_B(unsigned a, ull& x, ull& y) {   // +640: node-B buffer
    asm volatile("ld.shared.v2.b64 {%0, %1}, [%2+640];" : "=l"(x), "=l"(y) : "r"(a));
}
__device__ __forceinline__ void sts_f(unsigned a, float v) {
    asm volatile("st.shared.f32 [%0], %1;" :: "r"(a), "f"(v));
}
__device__ __forceinline__ void sts_f_B(unsigned a, float v) {
    asm volatile("st.shared.f32 [%0+640], %1;" :: "r"(a), "f"(v));
}
__device__ __forceinline__ ull pack2(float lo, float hi) {
    ull d; asm("mov.b64 %0, {%1, %2};" : "=l"(d) : "f"(lo), "f"(hi)); return d;
}
__device__ __forceinline__ void unpack2(float& lo, float& hi, ull v) {
    asm("mov.b64 {%0, %1}, %2;" : "=f"(lo), "=f"(hi) : "l"(v));
}
__device__ __forceinline__ ull mul2(ull a, ull b) {
    ull d; asm("mul.rn.f32x2 %0, %1, %2;" : "=l"(d) : "l"(a), "l"(b)); return d;
}
__device__ __forceinline__ ull fma2(ull a, ull b, ull c) {
    ull d; asm("fma.rn.f32x2 %0, %1, %2, %3;" : "=l"(d) : "l"(a), "l"(b), "l"(c)); return d;
}

// ---------------- launch 1: tables + classify + symmetrize ---------------
// grid 86 x 1024: bid 0 = tables, bid 1 = classify, bid 2..85 = sym
__global__ __launch_bounds__(1024) void k_prep(
    const float* __restrict__ y, const float* __restrict__ U3,
    const float* __restrict__ U2) {
    __shared__ float s[NM_];
    __shared__ int wcnt[32][E_];
    int t = threadIdx.x;
    int bid = blockIdx.x;

    if (bid == 0) {
        for (int j2 = t; j2 < NJ2_; j2 += 1024) {
            unsigned code;
            if (j2 < NP_) {
                int b = 0;
                while ((b + 1) * (b + 2) / 2 <= j2) b++;
                int a = j2 - b * (b + 1) / 2;
                code = (unsigned)a | ((unsigned)b << 4);
            } else if (j2 < NP_ + L_) {
                code = (unsigned)(j2 - NP_) | (1u << 8);
            } else {
                code = (1u << 8);
            }
            g_pcode[j2] = (unsigned short)code;
        }
        // quad-slot tables: slots grouped by d, p in steps of 4
        if (t < 16) {
            int d = t;
            int off = 0;
            for (int d2 = 0; d2 < d; d2++) { int P = (d2 + 1) * (d2 + 2) / 2; off += (P + 3) >> 2; }
            int P = (d + 1) * (d + 2) / 2;
            for (int p = 0; p < P; p += 4) {
                int qs = off + (p >> 2);
                g_qcode[qs] = (unsigned short)(p | (d << 8));
                #pragma unroll
                for (int k = 0; k < 4; k++)
                    g_ds_feat[qs * 4 + k] = (p + k < P) ? (unsigned short)(Tet(d) + p + k)
                                                        : (unsigned short)0xFFFF;
            }
        }
        if (t == 16) {
            for (int qs = 210; qs < NQS_; qs++) {        // 210 real slots
                g_qcode[qs] = 0;
                #pragma unroll
                for (int k = 0; k < 4; k++) g_ds_feat[qs * 4 + k] = 0xFFFF;
            }
        }
    } else if (bid == 1) {
        // atomic-free deterministic classify: 1024 threads = B_
        int b = t;
        int e = 0;
        #pragma unroll
        for (int j = 0; j < E_; j++)
            if (y[b * E_ + j] > 0.5f) e = j;
        int warp = t >> 5, lane = t & 31;
        unsigned m = __match_any_sync(0xffffffffu, e);
        int rank = __popc(m & ((1u << lane) - 1u));
        int ldr = __ffs(m) - 1;
        if (t < 32 * E_) ((int*)wcnt)[t] = 0;
        __syncthreads();
        if (lane == ldr) wcnt[warp][e] = __popc(m);
        __syncthreads();
        int off = 0;
        for (int w = 0; w < warp; w++) off += wcnt[w][e];
        g_nodes[e * B_ + off + rank] = b;
        if (t < E_) {
            int tot = 0;
            #pragma unroll
            for (int w = 0; w < 32; w++) tot += wcnt[w][t];
            g_cnt[t] = tot;
        }
    } else if (bid < 71) {        // 69 U3-sym blocks
        int b2 = bid - 2;
        int w = b2 / P3_, k = b2 % P3_;
        for (int i = t; i < NM_; i += 1024) s[i] = 0.f;
        __syncthreads();
        for (int idx = t; idx < 4096; idx += 1024) {
            int xx = idx >> 8, v = (idx >> 4) & 15, i = idx & 15;
            float val = U3[((((w * L_ + xx) * L_ + v) * L_ + i) * P3_) + k];
            int hi = max(xx, max(v, i));
            int lo = min(xx, min(v, i));
            int mid = xx + v + i - hi - lo;
            int mm = Tet(hi) + mid * (mid + 1) / 2 + lo;
            atomicAdd(&s[mm], val);
        }
        __syncthreads();
        for (int mm = t; mm < NM_; mm += 1024)
            g_U3sym[(w * NM_ + mm) * P3_ + k] = s[mm];
    } else if (bid < 86) {        // 15 U2-sym blocks
        int b2 = bid - 71;
        int w = b2 / P2_, k = b2 % P2_;
        if (t < NP_) s[t] = 0.f;
        __syncthreads();
        if (t < 256) {
            int xx = t >> 4, v = t & 15;
            float val = U2[((w * L_ + xx) * L_ + v) * P2_ + k];
            int hi = max(xx, v), lo = min(xx, v);
            int p = hi * (hi + 1) / 2 + lo;
            atomicAdd(&s[p], val);
        }
        __syncthreads();
        if (t < NP_)
            g_U2sym[(w * NP_ + t) * P2_ + k] = s[t];
    }
}

// ---------------- launch 2: coefficient build ----------------------------
// grid 3840 x 256: bid<960 triple GEMM tile (48 row-tiles x 20 ec-tiles);
//                  else pair/x tail (2880 blocks)
__global__ __launch_bounds__(256) void k_coeff(
    const float* __restrict__ wmax, const float* __restrict__ U1,
    const float* __restrict__ w2, const float* __restrict__ w1) {
    __shared__ float us[64][24];
    __shared__ __align__(8) float ws[P3_][64];
    __shared__ float outs[64][65];
    int t = threadIdx.x;
    int bid = blockIdx.x;

    if (bid < 960) {
        int row0 = (bid % 48) * 64;       // rows = EQ_*NJ3_ = 3072 exactly
        int ec0 = (bid / 48) * 64;
        int e = ec0 >> 7, c0 = ec0 & 127;

        for (int idx = t; idx < 64 * P3_; idx += 256) {
            int rr = idx / P3_, k = idx % P3_;
            int row = row0 + rr;
            int w = row >> 10, jj = row & 1023;       // NJ3_ = 1024
            int m = g_ds_feat[jj];
            us[rr][k] = (m != 0xFFFF) ? g_U3sym[(w * NM_ + m) * P3_ + k] : 0.f;
        }
        for (int idx = t; idx < P3_ * 64; idx += 256) {
            int k = idx >> 6, cc = idx & 63;
            ws[k][cc] = wmax[(e * P3_ + k) * C_ + c0 + cc];
        }
        __syncthreads();

        // f32x2 inner product: thread owns column pair (2*cc2, 2*cc2+1), 8 rows
        int cc2 = t & 31, rg = t >> 5;
        ull wp[P3_];
        #pragma unroll
        for (int k = 0; k < P3_; k++) wp[k] = *(const ull*)&ws[k][cc2 * 2];
        #pragma unroll
        for (int rs = 0; rs < 8; rs++) {
            int rr = rg * 8 + rs;
            ull acc = 0ull;
            #pragma unroll
            for (int k = 0; k < P3_; k++) {
                float u = us[rr][k];
                acc = fma2(pack2(u, u), wp[k], acc);
            }
            float lo, hi; unpack2(lo, hi, acc);
            outs[cc2 * 2][rr] = lo;
            outs[cc2 * 2 + 1][rr] = hi;
        }
        __syncthreads();

        for (int idx = t; idx < 64 * 64; idx += 256) {
            int c2 = idx >> 6, rr = idx & 63;
            int row = row0 + rr;
            int w = row >> 10, jj = row & 1023;
            g_coeff[(size_t)(ec0 + c2) * CW_ + w * NF_ + jj] = outs[c2][rr];
        }
    } else {
        int i = (bid - 960) * 256 + t;     // exactly 2880*256 = 737280 outputs
        int j2 = i % NJ2_;
        int w  = (i / NJ2_) % EQ_;
        int ec = i / (NJ2_ * EQ_);
        int e = ec >> 7, c = ec & 127;
        float sv = 0.f;
        if (j2 < NP_) {
            #pragma unroll
            for (int k = 0; k < P2_; k++)
                sv += g_U2sym[(w * NP_ + j2) * P2_ + k] * __ldg(&w2[(e * P2_ + k) * C_ + c]);
        } else if (j2 < NP_ + L_) {
            sv = __ldg(&U1[w * L_ + (j2 - NP_)]) * __ldg(&w1[e * C_ + c]);
        }
        g_coeff[(size_t)ec * CW_ + w * NF_ + NJ3_ + j2] = sv;
    }
}

// ---------------- launch 3: main — block per (c,e) -----------------------
// 4 warp-pairs per block; each pair processes 2 nodes per iteration.
// SINGLE barrier per iteration: zp + s_red are parity double-buffered, and
// the output epilogue is pipelined one iteration behind (finalized after the
// NEXT iteration's barrier; trailing PBAR drains).
// zp[parity][pw]: [0,136) pair values, [152] sink; node B at +640 bytes.
// x in registers: lanes 0-15 hold x[i], lanes 16-31 hold 1.0f.
__global__ __launch_bounds__(256, 2) void k_main(
    const float* __restrict__ x, float* __restrict__ out) {
    __shared__ __align__(16) float zp[2][4][512];   // parity stride = 8192 B
    __shared__ float s_red[2][4][6];

    int t = threadIdx.x;
    int warp = t >> 5, lane = t & 31;
    int pw = warp >> 1;
    int half = warp & 1;
    int c = blockIdx.x, e = blockIdx.y;

    const float* cfb = g_coeff + (size_t)(e * C_ + c) * CW_;
    unsigned zbA = (unsigned)__cvta_generic_to_shared(&zp[0][pw][0]);

    // quad-step coefficients (2 ull per step per w) + addresses + x lanes
    ull cd0[8], cd1[8], cd2[8];
    unsigned zsa[4]; int didx[4];
    #pragma unroll
    for (int r = 0; r < 4; r++) {
        int slot = (half * 4 + r) * 32 + lane;
        int j = slot * 4;
        cd0[2*r]   = *(const ull*)(cfb + 0 * NF_ + j);
        cd0[2*r+1] = *(const ull*)(cfb + 0 * NF_ + j + 2);
        cd1[2*r]   = *(const ull*)(cfb + 1 * NF_ + j);
        cd1[2*r+1] = *(const ull*)(cfb + 1 * NF_ + j + 2);
        cd2[2*r]   = *(const ull*)(cfb + 2 * NF_ + j);
        cd2[2*r+1] = *(const ull*)(cfb + 2 * NF_ + j + 2);
        unsigned cc = g_qcode[slot];
        zsa[r] = zbA + (cc & 255u) * 4u;
        didx[r] = cc >> 8;
    }
    // pair-region coefficients + shfl source lanes + store addresses
    float cp0[3], cp1[3], cp2[3];
    int aidx[3], bidx[3]; unsigned sta[3];
    #pragma unroll
    for (int r = 0; r < 3; r++) {
        int j2 = (half * 3 + r) * 32 + lane;
        cp0[r] = cfb[0 * NF_ + NJ3_ + j2];
        cp1[r] = cfb[1 * NF_ + NJ3_ + j2];
        cp2[r] = cfb[2 * NF_ + NJ3_ + j2];
        unsigned cc = g_pcode[j2];
        aidx[r] = cc & 15u;
        bidx[r] = (cc & 256u) ? 16 : ((cc >> 4) & 15u);  // pairs: b lane; isx/pad: lane 16 (=1.0f)
        sta[r] = (j2 < NP_) ? (zbA + (unsigned)j2 * 4u) : (zbA + 152u * 4u);
    }

    int nb = g_cnt[e];
    int jnA = pw * 2;

    // prime: node indices + x prefetch for first iteration
    int bA = (jnA < nb) ? g_nodes[e * B_ + jnA] : -1;
    int bB = (jnA + 1 < nb) ? g_nodes[e * B_ + jnA + 1] : -1;
    float xnA = 1.0f, xnB = 1.0f;
    if (lane < L_) {
        xnA = (bA >= 0) ? __ldg(&x[((size_t)bA * C_ + c) * L_ + lane]) : 0.f;
        xnB = (bB >= 0) ? __ldg(&x[((size_t)bB * C_ + c) * L_ + lane]) : 0.f;
    }

    int wsel = lane >> 3;                 // 0..3 (octet id; 3 unused)
    bool owner = (lane == 0) | (lane == 8) | (lane == 16);

    // pipelined-epilogue state
    float pvA = 0.f, pvB = 0.f;
    int pbA = -1, pbB = -1;
    int par = 0;
    int poff = 8192;                      // parity toggle (+/- 8192 bytes)

    #define PBAR() asm volatile("bar.sync %0, 64;" :: "r"(pw + 1) : "memory")

    for (; jnA < nb; jnA += 8) {
        float xvA = xnA, xvB = xnB;
        int bcA = bA, bcB = bB;
        int jn2 = jnA + 8;
        bA = (jn2 < nb) ? g_nodes[e * B_ + jn2] : -1;
        bB = (jn2 + 1 < nb) ? g_nodes[e * B_ + jn2 + 1] : -1;

        // pair/x region for both nodes: value -> dot contribution + zp store
        float s0A = 0.f, s1A = 0.f, s2A = 0.f;
        float s0B = 0.f, s1B = 0.f, s2B = 0.f;
        #pragma unroll
        for (int r = 0; r < 3; r++) {
            float vaA = __shfl_sync(0xffffffffu, xvA, aidx[r]);
            float vbA = __shfl_sync(0xffffffffu, xvA, bidx[r]);
            float vaB = __shfl_sync(0xffffffffu, xvB, aidx[r]);
            float vbB = __shfl_sync(0xffffffffu, xvB, bidx[r]);
            float valA = vaA * vbA;
            float valB = vaB * vbB;
            sts_f(sta[r], valA);
            sts_f_B(sta[r], valB);
            s0A = fmaf(cp0[r], valA, s0A);
            s1A = fmaf(cp1[r], valA, s1A);
            s2A = fmaf(cp2[r], valA, s2A);
            s0B = fmaf(cp0[r], valB, s0B);
            s1B = fmaf(cp1[r], valB, s1B);
            s2B = fmaf(cp2[r], valB, s2B);
        }
        // next-iteration x prefetch (hidden behind quad phase)
        xnA = 1.0f; xnB = 1.0f;
        if (lane < L_) {
            xnA = (bA >= 0) ? __ldg(&x[((size_t)bA * C_ + c) * L_ + lane]) : 0.f;
            xnB = (bB >= 0) ? __ldg(&x[((size_t)bB * C_ + c) * L_ + lane]) : 0.f;
        }

        PBAR();   // the ONLY barrier: publishes this iter's zp; also makes
                  // partner's PREVIOUS-iter s_red publish visible

        // pipelined epilogue for the previous iteration (reads s_red[par^1])
        if (owner) {
            if (half == 0) {
                if (pbA >= 0)
                    out[((size_t)pbA * C_ + c) * EQ_ + wsel] = pvA + s_red[par ^ 1][pw][wsel];
            } else {
                if (pbB >= 0)
                    out[((size_t)pbB * C_ + c) * EQ_ + wsel] = pvB + s_red[par ^ 1][pw][3 + wsel];
            }
        }

        // fused triple dot: 4 quad steps x 2 nodes, packed f32x2
        ull a0A = 0ull, a1A = 0ull, a2A = 0ull;
        ull a0B = 0ull, a1B = 0ull, a2B = 0ull;
        #pragma unroll
        for (int r = 0; r < 4; r++) {
            ull zA0, zA1, zB0, zB1;
            lds128(zsa[r], zA0, zA1);
            lds128_B(zsa[r], zB0, zB1);
            float xdA = __shfl_sync(0xffffffffu, xvA, didx[r]);
            float xdB = __shfl_sync(0xffffffffu, xvB, didx[r]);
            ull xpA = pack2(xdA, xdA);
            ull xpB = pack2(xdB, xdB);
            ull tA0 = mul2(zA0, xpA), tA1 = mul2(zA1, xpA);
            ull tB0 = mul2(zB0, xpB), tB1 = mul2(zB1, xpB);
            a0A = fma2(cd0[2*r], tA0, a0A); a0A = fma2(cd0[2*r+1], tA1, a0A);
            a1A = fma2(cd1[2*r], tA0, a1A); a1A = fma2(cd1[2*r+1], tA1, a1A);
            a2A = fma2(cd2[2*r], tA0, a2A); a2A = fma2(cd2[2*r+1], tA1, a2A);
            a0B = fma2(cd0[2*r], tB0, a0B); a0B = fma2(cd0[2*r+1], tB1, a0B);
            a1B = fma2(cd1[2*r], tB0, a1B); a1B = fma2(cd1[2*r+1], tB1, a1B);
            a2B = fma2(cd2[2*r], tB0, a2B); a2B = fma2(cd2[2*r+1], tB1, a2B);
        }
        float lo, hi;
        unpack2(lo, hi, a0A); float r0A = s0A + lo + hi;
        unpack2(lo, hi, a1A); float r1A = s1A + lo + hi;
        unpack2(lo, hi, a2A); float r2A = s2A + lo + hi;
        unpack2(lo, hi, a0B); float r0B = s0B + lo + hi;
        unpack2(lo, hi, a1B); float r1B = s1B + lo + hi;
        unpack2(lo, hi, a2B); float r2B = s2B + lo + hi;

        // reduce: xor{16,8} on all six, octet-select, xor{4,2,1}
        #pragma unroll
        for (int msk = 16; msk >= 8; msk >>= 1) {
            r0A += __shfl_xor_sync(0xffffffffu, r0A, msk);
            r1A += __shfl_xor_sync(0xffffffffu, r1A, msk);
            r2A += __shfl_xor_sync(0xffffffffu, r2A, msk);
            r0B += __shfl_xor_sync(0xffffffffu, r0B, msk);
            r1B += __shfl_xor_sync(0xffffffffu, r1B, msk);
            r2B += __shfl_xor_sync(0xffffffffu, r2B, msk);
        }
        float vA = (lane < 8) ? r0A : (lane < 16) ? r1A : r2A;
        float vB = (lane < 8) ? r0B : (lane < 16) ? r1B : r2B;
        #pragma unroll
        for (int msk = 4; msk >= 1; msk >>= 1) {
            vA += __shfl_xor_sync(0xffffffffu, vA, msk);
            vB += __shfl_xor_sync(0xffffffffu, vB, msk);
        }
        // publish this iteration's half-sums (consumed after NEXT barrier)
        if (owner) {
            if (half == 1) s_red[par][pw][wsel] = vA;       // half1 publishes A
            else           s_red[par][pw][3 + wsel] = vB;   // half0 publishes B
        }
        pvA = vA; pvB = vB; pbA = bcA; pbB = bcB;

        // toggle parity buffers
        #pragma unroll
        for (int r = 0; r < 4; r++) zsa[r] += poff;
        #pragma unroll
        for (int r = 0; r < 3; r++) sta[r] += poff;
        poff = -poff;
        par ^= 1;
    }

    // drain the pipelined epilogue
    PBAR();
    if (owner) {
        if (half == 0) {
            if (pbA >= 0)
                out[((size_t)pbA * C_ + c) * EQ_ + wsel] = pvA + s_red[par ^ 1][pw][wsel];
        } else {
            if (pbB >= 0)
                out[((size_t)pbB * C_ + c) * EQ_ + wsel] = pvB + s_red[par ^ 1][pw][3 + wsel];
        }
    }
    #undef PBAR
}

extern "C" void kernel_launch(void* const* d_in, const int* in_sizes, int n_in,
                              void* d_out, int out_size) {
    const float* x    = (const float*)d_in[0];
    const float* y    = (const float*)d_in[1];
    const float* U3   = (const float*)d_in[2];
    const float* U2   = (const float*)d_in[3];
    const float* U1   = (const float*)d_in[4];
    const float* wmax = (const float*)d_in[5];
    const float* w2   = (const float*)d_in[6];
    const float* w1   = (const float*)d_in[7];
    float* out = (float*)d_out;

    k_prep<<<86, 1024>>>(y, U3, U2);
    k_coeff<<<3840, 256>>>(wmax, U1, w2, w1);
    k_main<<<dim3(C_, E_), 256>>>(x, out);
}